// round 7
// baseline (speedup 1.0000x reference)
#include <cuda_runtime.h>
#include <cstdint>
#include <cstddef>

#define CDIM 224
#define SCALE_Q 0.18898223650461363f
#define STAGE_FLOATS 13056   // 256*36 (A) + 32*120 (B)
#define NSTAGE 3
#define GEMM_SMEM_BYTES (NSTAGE * STAGE_FLOATS * 4)

__device__ float g_Q[29360128];
__device__ float g_K[29360128];
__device__ float g_V[29360128];
__device__ float g_Attn[29360128];
__device__ float g_X[29360128];       // tf32-rounded x
__device__ float g_Wq[50176];         // tf32-rounded weights
__device__ float g_Wkv[100352];
__device__ float g_Wout[50176];

__device__ __forceinline__ float tf32f(float f) {
    unsigned u; asm("cvt.rna.tf32.f32 %0, %1;" : "=r"(u) : "f"(f));
    return __uint_as_float(u);
}
__device__ __forceinline__ void cp16(float* smem_dst, const float* gsrc) {
    unsigned s = (unsigned)__cvta_generic_to_shared(smem_dst);
    asm volatile("cp.async.cg.shared.global [%0], [%1], 16;" :: "r"(s), "l"(gsrc) : "memory");
}

// ---------------- prepass: RN-round fp32 -> tf32 bits ----------------
__global__ __launch_bounds__(256) void round_tf32(
    const float* __restrict__ src, float* __restrict__ dst, int n4)
{
    int i = blockIdx.x * blockDim.x + threadIdx.x;
    if (i < n4) {
        float4 f = reinterpret_cast<const float4*>(src)[i];
        reinterpret_cast<float4*>(dst)[i] =
            make_float4(tf32f(f.x), tf32f(f.y), tf32f(f.z), tf32f(f.w));
    }
}

// ---------------- 3-stage pipelined GEMM: BM=256 BN=112 BK=32, K=224, 256 thr ----------------
// warps 4m x 2n, warp tile 64x56; inputs already tf32-rounded; no cvt in hot loop
__device__ __forceinline__ void gemm_mainloop(
    const float* __restrict__ A, const float* __restrict__ B, int ldb, int ncol0,
    float* smem, float (&acc)[4][7][4])
{
    const int tid = threadIdx.x;
    const int wid = tid >> 5, lane = tid & 31;
    const int g = lane >> 2, tig = lane & 3;
    const int wm = wid >> 1, wn = wid & 1;

    const int ar = tid >> 3, ac4 = (tid & 7) << 2;   // A: rows ar + p*32, p=0..7
    const int brq[4] = { tid / 28, (tid + 256) / 28, (tid + 512) / 28, (tid + 768) / 28 };
    const int bc4[4] = { (tid % 28) << 2, ((tid + 256) % 28) << 2, ((tid + 512) % 28) << 2, ((tid + 768) % 28) << 2 };

    auto issue = [&](int kt, int stage) {
        float* sA = smem + stage * STAGE_FLOATS;
        float* sB = sA + 9216;
        #pragma unroll
        for (int p = 0; p < 8; p++) {
            int r = ar + p * 32;
            cp16(sA + r * 36 + ac4, A + (size_t)r * CDIM + kt + ac4);
        }
        #pragma unroll
        for (int p = 0; p < 4; p++) {
            int q = tid + p * 256;
            if (q < 896)
                cp16(sB + brq[p] * 120 + bc4[p], B + (size_t)(kt + brq[p]) * ldb + ncol0 + bc4[p]);
        }
        asm volatile("cp.async.commit_group;" ::: "memory");
    };

    issue(0, 0);
    issue(32, 1);
    #pragma unroll
    for (int it = 0; it < 7; it++) {
        if (it == 6) asm volatile("cp.async.wait_group 0;" ::: "memory");
        else         asm volatile("cp.async.wait_group 1;" ::: "memory");
        __syncthreads();
        if (it + 2 < 7) issue((it + 2) * 32, (it + 2) % NSTAGE);
        float* sA = smem + (it % NSTAGE) * STAGE_FLOATS;
        float* sB = sA + 9216;
        #pragma unroll
        for (int ks = 0; ks < 4; ks++) {
            const int kb = ks * 8;
            unsigned af[4][4];
            #pragma unroll
            for (int mt = 0; mt < 4; mt++) {
                int m = wm * 64 + mt * 16 + g;
                af[mt][0] = __float_as_uint(sA[m * 36 + kb + tig]);
                af[mt][1] = __float_as_uint(sA[(m + 8) * 36 + kb + tig]);
                af[mt][2] = __float_as_uint(sA[m * 36 + kb + tig + 4]);
                af[mt][3] = __float_as_uint(sA[(m + 8) * 36 + kb + tig + 4]);
            }
            unsigned bf[7][2];
            #pragma unroll
            for (int nt = 0; nt < 7; nt++) {
                int n = wn * 56 + nt * 8 + g;
                bf[nt][0] = __float_as_uint(sB[(kb + tig) * 120 + n]);
                bf[nt][1] = __float_as_uint(sB[(kb + tig + 4) * 120 + n]);
            }
            #pragma unroll
            for (int mt = 0; mt < 4; mt++)
                #pragma unroll
                for (int nt = 0; nt < 7; nt++)
                    asm volatile(
                        "mma.sync.aligned.m16n8k8.row.col.f32.tf32.tf32.f32 "
                        "{%0,%1,%2,%3}, {%4,%5,%6,%7}, {%8,%9}, {%0,%1,%2,%3};\n"
                        : "+f"(acc[mt][nt][0]), "+f"(acc[mt][nt][1]),
                          "+f"(acc[mt][nt][2]), "+f"(acc[mt][nt][3])
                        : "r"(af[mt][0]), "r"(af[mt][1]), "r"(af[mt][2]), "r"(af[mt][3]),
                          "r"(bf[nt][0]), "r"(bf[nt][1]));
        }
        __syncthreads();
    }
}

// ---------------- kernel 1: QKV + window-partition permute + q*SCALE ----------------
__global__ __launch_bounds__(256, 1) void qkv_kernel()
{
    extern __shared__ float smem[];
    float acc[4][7][4] = {};
    const int ctan = blockIdx.x, ctam = blockIdx.y;

    const float* B; int ldb, ncol0;
    if (ctan < 2) { B = g_Wq;  ldb = 224; ncol0 = ctan * 112; }
    else          { B = g_Wkv; ldb = 448; ncol0 = ctan * 112 - 224; }

    gemm_mainloop(g_X + (size_t)ctam * 256 * CDIM, B, ldb, ncol0, smem, acc);

    float* Dst = (ctan < 2) ? g_Q : (ctan < 4 ? g_K : g_V);
    const float scale = (ctan < 2) ? SCALE_Q : 1.0f;
    const int tid = threadIdx.x, wid = tid >> 5, lane = tid & 31;
    const int g = lane >> 2, tig = lane & 3, wm = wid >> 1, wn = wid & 1;
    const int joff = (ctan & 1) * 112 + wn * 56 + tig * 2;

    #pragma unroll
    for (int mt = 0; mt < 4; mt++)
        #pragma unroll
        for (int rh = 0; rh < 2; rh++) {
            int r = wm * 64 + mt * 16 + rh * 8 + g;
            int t = ctam * 256 + r;
            int b = t >> 10, hr = (t >> 5) & 31, wc = t & 31;
            int n = ((hr >> 3) << 2) + (wc >> 3);
            int i = ((hr & 7) << 3) + (wc & 7);
            float* base = Dst + ((size_t)((b * 16 + n) * 64 + i)) * CDIM + joff;
            #pragma unroll
            for (int nt = 0; nt < 7; nt++)
                *reinterpret_cast<float2*>(base + nt * 8) =
                    make_float2(acc[mt][nt][rh * 2 + 0] * scale, acc[mt][nt][rh * 2 + 1] * scale);
        }
}

// ---------------- kernel 2: local window attention (channels 0..111) ----------------
__global__ __launch_bounds__(256) void local_attn(const float* __restrict__ pe1)
{
    __shared__ float qT[28 * 68];
    __shared__ float kT[28 * 68];
    __shared__ float sSP[64 * 68];
    __shared__ float sV[64 * 28 + 4];

    const int tid = threadIdx.x;
    const size_t rowbase = (size_t)blockIdx.x * 64 * CDIM;
    const int tr = tid >> 4, tc = tid & 15;
    const int sr = tid >> 2, sc0 = (tid & 3) << 4;

    for (int h = 0; h < 4; h++) {
        const int ch0 = h * 28;
        #pragma unroll
        for (int p = 0; p < 2; p++) {
            int idx = tid + p * 256;
            if (idx < 448) {
                int rr = idx / 7, c4 = (idx % 7) << 2;
                size_t ga = rowbase + (size_t)rr * CDIM + ch0 + c4;
                float4 q4 = *reinterpret_cast<const float4*>(g_Q + ga);
                qT[(c4 + 0) * 68 + rr] = q4.x; qT[(c4 + 1) * 68 + rr] = q4.y;
                qT[(c4 + 2) * 68 + rr] = q4.z; qT[(c4 + 3) * 68 + rr] = q4.w;
                float4 k4 = *reinterpret_cast<const float4*>(g_K + ga);
                kT[(c4 + 0) * 68 + rr] = k4.x; kT[(c4 + 1) * 68 + rr] = k4.y;
                kT[(c4 + 2) * 68 + rr] = k4.z; kT[(c4 + 3) * 68 + rr] = k4.w;
                *reinterpret_cast<float4*>(sV + rr * 28 + c4) =
                    *reinterpret_cast<const float4*>(g_V + ga);
            }
        }
        __syncthreads();
        float accS[16];
        #pragma unroll
        for (int u = 0; u < 16; u++) accS[u] = 0.f;
        #pragma unroll
        for (int kk = 0; kk < 28; kk++) {
            float4 qv = *reinterpret_cast<float4*>(qT + kk * 68 + 4 * tr);
            float4 kv = *reinterpret_cast<float4*>(kT + kk * 68 + 4 * tc);
            float qa[4] = {qv.x, qv.y, qv.z, qv.w};
            float ka[4] = {kv.x, kv.y, kv.z, kv.w};
            #pragma unroll
            for (int i = 0; i < 4; i++)
                #pragma unroll
                for (int j = 0; j < 4; j++) accS[i * 4 + j] += qa[i] * ka[j];
        }
        #pragma unroll
        for (int i = 0; i < 4; i++)
            *reinterpret_cast<float4*>(sSP + (4 * tr + i) * 68 + 4 * tc) =
                make_float4(accS[i * 4], accS[i * 4 + 1], accS[i * 4 + 2], accS[i * 4 + 3]);
        __syncthreads();
        float vals[16];
        const float* pr = pe1 + ((size_t)(h * 64 + sr)) * 64 + sc0;
        #pragma unroll
        for (int u = 0; u < 4; u++) {
            float4 sv = *reinterpret_cast<float4*>(sSP + sr * 68 + sc0 + 4 * u);
            float4 pv = *reinterpret_cast<const float4*>(pr + 4 * u);
            vals[4 * u + 0] = sv.x + pv.x; vals[4 * u + 1] = sv.y + pv.y;
            vals[4 * u + 2] = sv.z + pv.z; vals[4 * u + 3] = sv.w + pv.w;
        }
        float m = vals[0];
        #pragma unroll
        for (int u = 1; u < 16; u++) m = fmaxf(m, vals[u]);
        m = fmaxf(m, __shfl_xor_sync(0xffffffffu, m, 1));
        m = fmaxf(m, __shfl_xor_sync(0xffffffffu, m, 2));
        float sum = 0.f;
        #pragma unroll
        for (int u = 0; u < 16; u++) { vals[u] = __expf(vals[u] - m); sum += vals[u]; }
        sum += __shfl_xor_sync(0xffffffffu, sum, 1);
        sum += __shfl_xor_sync(0xffffffffu, sum, 2);
        const float inv = 1.f / sum;
        __syncthreads();
        #pragma unroll
        for (int u = 0; u < 16; u++) sSP[(sc0 + u) * 68 + sr] = vals[u] * inv;  // P^T
        __syncthreads();
        float accO[8];
        #pragma unroll
        for (int u = 0; u < 8; u++) accO[u] = 0.f;
        const int cc = (tc < 14) ? (2 * tc) : 0;
        #pragma unroll 8
        for (int j = 0; j < 64; j++) {
            float4 pv = *reinterpret_cast<float4*>(sSP + j * 68 + 4 * tr);
            float2 vv = *reinterpret_cast<float2*>(sV + j * 28 + cc);
            float pa[4] = {pv.x, pv.y, pv.z, pv.w};
            #pragma unroll
            for (int i = 0; i < 4; i++) {
                accO[i * 2 + 0] += pa[i] * vv.x;
                accO[i * 2 + 1] += pa[i] * vv.y;
            }
        }
        if (tc < 14)
            #pragma unroll
            for (int i = 0; i < 4; i++)
                *reinterpret_cast<float2*>(g_Attn + rowbase + (size_t)(4 * tr + i) * CDIM + ch0 + 2 * tc) =
                    make_float2(tf32f(accO[i * 2]), tf32f(accO[i * 2 + 1]));
        __syncthreads();
    }
}

// ---------------- kernel 3: global attention (channels 112..223) ----------------
__global__ __launch_bounds__(128) void global_attn(const float* __restrict__ pe2)
{
    __shared__ float qs[16 * 116];
    __shared__ float kTs[112 * 20];
    __shared__ float vs[16 * 116];
    __shared__ float ps[4 * 16 * 17];

    const int tid = threadIdx.x;
    const int b = blockIdx.x >> 6, ipos = blockIdx.x & 63;
    const size_t base0 = ((size_t)(b * 16) * 64 + ipos) * CDIM + 112;

    #pragma unroll
    for (int p = 0; p < 4; p++) {
        int idx = tid + p * 128;
        if (idx < 448) {
            int n = idx / 28, c4 = (idx % 28) << 2;
            size_t ga = base0 + (size_t)n * (64 * CDIM) + c4;
            *reinterpret_cast<float4*>(qs + n * 116 + c4) = *reinterpret_cast<const float4*>(g_Q + ga);
            *reinterpret_cast<float4*>(vs + n * 116 + c4) = *reinterpret_cast<const float4*>(g_V + ga);
            float4 k4 = *reinterpret_cast<const float4*>(g_K + ga);
            kTs[(c4 + 0) * 20 + n] = k4.x; kTs[(c4 + 1) * 20 + n] = k4.y;
            kTs[(c4 + 2) * 20 + n] = k4.z; kTs[(c4 + 3) * 20 + n] = k4.w;
        }
    }
    __syncthreads();

    const int h = tid >> 5, lane = tid & 31;
    const int r = lane >> 1, cb = (lane & 1) << 3;

    float qreg[28];
    #pragma unroll
    for (int u = 0; u < 7; u++) {
        float4 f = *reinterpret_cast<float4*>(qs + r * 116 + h * 28 + 4 * u);
        qreg[4 * u] = f.x; qreg[4 * u + 1] = f.y; qreg[4 * u + 2] = f.z; qreg[4 * u + 3] = f.w;
    }
    float s[8];
    #pragma unroll
    for (int j = 0; j < 8; j++) s[j] = 0.f;
    #pragma unroll
    for (int d = 0; d < 28; d++)
        #pragma unroll
        for (int j = 0; j < 8; j++) s[j] += qreg[d] * kTs[(h * 28 + d) * 20 + cb + j];

    const float* pr = pe2 + (size_t)h * 256 + r * 16 + cb;
    #pragma unroll
    for (int j = 0; j < 8; j++) s[j] += pr[j];
    float m = s[0];
    #pragma unroll
    for (int j = 1; j < 8; j++) m = fmaxf(m, s[j]);
    m = fmaxf(m, __shfl_xor_sync(0xffffffffu, m, 1));
    float sum = 0.f;
    #pragma unroll
    for (int j = 0; j < 8; j++) { s[j] = __expf(s[j] - m); sum += s[j]; }
    sum += __shfl_xor_sync(0xffffffffu, sum, 1);
    const float inv = 1.f / sum;
    #pragma unroll
    for (int j = 0; j < 8; j++) ps[h * 272 + r * 17 + cb + j] = s[j] * inv;
    __syncwarp();

    const int chb = (lane & 1) * 14;
    float accO[14];
    #pragma unroll
    for (int c = 0; c < 14; c++) accO[c] = 0.f;
    #pragma unroll
    for (int j = 0; j < 16; j++) {
        float p = ps[h * 272 + r * 17 + j];
        #pragma unroll
        for (int c = 0; c < 14; c++) accO[c] += p * vs[j * 116 + h * 28 + chb + c];
    }
    float* od = g_Attn + ((size_t)((b * 16 + r) * 64 + ipos)) * CDIM + 112 + h * 28 + chb;
    #pragma unroll
    for (int c = 0; c < 14; c++) od[c] = tf32f(accO[c]);
}

// ---------------- kernel 4: out-proj + bias + window-reverse ----------------
__global__ __launch_bounds__(256, 1) void proj_kernel(
    const float* __restrict__ bout, float* __restrict__ out)
{
    extern __shared__ float smem[];
    float acc[4][7][4] = {};
    const int ctan = blockIdx.x, ctam = blockIdx.y;

    gemm_mainloop(g_Attn + (size_t)ctam * 256 * CDIM, g_Wout, 224, ctan * 112, smem, acc);

    const int tid = threadIdx.x, wid = tid >> 5, lane = tid & 31;
    const int g = lane >> 2, tig = lane & 3, wm = wid >> 1, wn = wid & 1;
    const int joff = ctan * 112 + wn * 56 + tig * 2;

    #pragma unroll
    for (int mt = 0; mt < 4; mt++)
        #pragma unroll
        for (int rh = 0; rh < 2; rh++) {
            int r = wm * 64 + mt * 16 + rh * 8 + g;
            int t = ctam * 256 + r;
            int b = t >> 10, n = (t >> 6) & 15, i = t & 63;
            int hr = (n >> 2) * 8 + (i >> 3), wc = (n & 3) * 8 + (i & 7);
            float* base = out + ((size_t)((b * 32 + hr) * 32 + wc)) * CDIM + joff;
            #pragma unroll
            for (int nt = 0; nt < 7; nt++) {
                float2 bo = *reinterpret_cast<const float2*>(bout + joff + nt * 8);
                *reinterpret_cast<float2*>(base + nt * 8) =
                    make_float2(acc[mt][nt][rh * 2 + 0] + bo.x, acc[mt][nt][rh * 2 + 1] + bo.y);
            }
        }
}

extern "C" void kernel_launch(void* const* d_in, const int* in_sizes, int n_in,
                              void* d_out, int out_size) {
    const float* x    = (const float*)d_in[0];
    const float* Wq   = (const float*)d_in[1];
    const float* Wkv  = (const float*)d_in[2];
    const float* Wout = (const float*)d_in[3];
    const float* bout = (const float*)d_in[4];
    const float* pe1  = (const float*)d_in[5];
    const float* pe2  = (const float*)d_in[6];
    float* out = (float*)d_out;

    cudaFuncSetAttribute(qkv_kernel,  cudaFuncAttributeMaxDynamicSharedMemorySize, GEMM_SMEM_BYTES);
    cudaFuncSetAttribute(proj_kernel, cudaFuncAttributeMaxDynamicSharedMemorySize, GEMM_SMEM_BYTES);

    float* gX;    cudaGetSymbolAddress((void**)&gX,    g_X);
    float* gWq;   cudaGetSymbolAddress((void**)&gWq,   g_Wq);
    float* gWkv;  cudaGetSymbolAddress((void**)&gWkv,  g_Wkv);
    float* gWout; cudaGetSymbolAddress((void**)&gWout, g_Wout);

    round_tf32<<<28672, 256>>>(x, gX, 29360128 / 4);
    round_tf32<<<49, 256>>>(Wq, gWq, 50176 / 4);
    round_tf32<<<98, 256>>>(Wkv, gWkv, 100352 / 4);
    round_tf32<<<49, 256>>>(Wout, gWout, 50176 / 4);

    qkv_kernel<<<dim3(6, 512), 256, GEMM_SMEM_BYTES>>>();
    local_attn<<<2048, 256>>>(pe1);
    global_attn<<<8192, 128>>>(pe2);
    proj_kernel<<<dim3(2, 512), 256, GEMM_SMEM_BYTES>>>(bout, out);
}

// round 8
// speedup vs baseline: 1.0986x; 1.0986x over previous
#include <cuda_runtime.h>
#include <cstdint>
#include <cstddef>

#define CDIM 224
#define SCALE_Q 0.18898223650461363f
#define STAGE_FLOATS 8448   // 128*36 (A) + 32*120 (B)
#define NSTAGE 3
#define GEMM_SMEM_BYTES (NSTAGE * STAGE_FLOATS * 4)

__device__ float g_Q[29360128];
__device__ float g_K[29360128];
__device__ float g_V[29360128];
__device__ float g_Attn[29360128];
__device__ float g_X[29360128];
__device__ float g_Wq[50176];
__device__ float g_Wkv[100352];
__device__ float g_Wout[50176];

__device__ __forceinline__ float tf32f(float f) {
    unsigned u; asm("cvt.rna.tf32.f32 %0, %1;" : "=r"(u) : "f"(f));
    return __uint_as_float(u);
}
__device__ __forceinline__ void cp16(float* smem_dst, const float* gsrc) {
    unsigned s = (unsigned)__cvta_generic_to_shared(smem_dst);
    asm volatile("cp.async.cg.shared.global [%0], [%1], 16;" :: "r"(s), "l"(gsrc) : "memory");
}
#define MMA_TF32(acc, a0,a1,a2,a3, b0,b1) \
    asm volatile("mma.sync.aligned.m16n8k8.row.col.f32.tf32.tf32.f32 " \
        "{%0,%1,%2,%3}, {%4,%5,%6,%7}, {%8,%9}, {%0,%1,%2,%3};\n" \
        : "+f"(acc[0]), "+f"(acc[1]), "+f"(acc[2]), "+f"(acc[3]) \
        : "r"(a0), "r"(a1), "r"(a2), "r"(a3), "r"(b0), "r"(b1))

// ---------------- prepass: RN-round fp32 -> tf32 bits ----------------
__global__ __launch_bounds__(256) void round_tf32(
    const float* __restrict__ src, float* __restrict__ dst, int n4)
{
    int i = blockIdx.x * blockDim.x + threadIdx.x;
    if (i < n4) {
        float4 f = reinterpret_cast<const float4*>(src)[i];
        reinterpret_cast<float4*>(dst)[i] =
            make_float4(tf32f(f.x), tf32f(f.y), tf32f(f.z), tf32f(f.w));
    }
}

// ---------------- 3-stage pipelined GEMM: BM=128 BN=112 BK=32, K=224, 256 thr ----------------
__device__ __forceinline__ void gemm_mainloop(
    const float* __restrict__ A, const float* __restrict__ B, int ldb, int ncol0,
    float* smem, float (&acc)[2][7][4])
{
    const int tid = threadIdx.x;
    const int wid = tid >> 5, lane = tid & 31;
    const int g = lane >> 2, tig = lane & 3;
    const int wm = wid >> 1, wn = wid & 1;

    const int ar = tid >> 3, ac4 = (tid & 7) << 2;
    const int brq[4] = { tid / 28, (tid + 256) / 28, (tid + 512) / 28, (tid + 768) / 28 };
    const int bc4[4] = { (tid % 28) << 2, ((tid + 256) % 28) << 2, ((tid + 512) % 28) << 2, ((tid + 768) % 28) << 2 };

    auto issue = [&](int kt, int stage) {
        float* sA = smem + stage * STAGE_FLOATS;
        float* sB = sA + 4608;
        #pragma unroll
        for (int p = 0; p < 4; p++) {
            int r = ar + p * 32;
            cp16(sA + r * 36 + ac4, A + (size_t)r * CDIM + kt + ac4);
        }
        #pragma unroll
        for (int p = 0; p < 4; p++) {
            int q = tid + p * 256;
            if (q < 896)
                cp16(sB + brq[p] * 120 + bc4[p], B + (size_t)(kt + brq[p]) * ldb + ncol0 + bc4[p]);
        }
        asm volatile("cp.async.commit_group;" ::: "memory");
    };

    issue(0, 0);
    issue(32, 1);
    #pragma unroll
    for (int it = 0; it < 7; it++) {
        if (it == 6) asm volatile("cp.async.wait_group 0;" ::: "memory");
        else         asm volatile("cp.async.wait_group 1;" ::: "memory");
        __syncthreads();
        float* sA = smem + (it % NSTAGE) * STAGE_FLOATS;
        float* sB = sA + 4608;
        #pragma unroll
        for (int ks = 0; ks < 4; ks++) {
            const int kb = ks * 8;
            unsigned af[2][4];
            #pragma unroll
            for (int mt = 0; mt < 2; mt++) {
                int m = wm * 32 + mt * 16 + g;
                af[mt][0] = __float_as_uint(sA[m * 36 + kb + tig]);
                af[mt][1] = __float_as_uint(sA[(m + 8) * 36 + kb + tig]);
                af[mt][2] = __float_as_uint(sA[m * 36 + kb + tig + 4]);
                af[mt][3] = __float_as_uint(sA[(m + 8) * 36 + kb + tig + 4]);
            }
            unsigned bf[7][2];
            #pragma unroll
            for (int nt = 0; nt < 7; nt++) {
                int n = wn * 56 + nt * 8 + g;
                bf[nt][0] = __float_as_uint(sB[(kb + tig) * 120 + n]);
                bf[nt][1] = __float_as_uint(sB[(kb + tig + 4) * 120 + n]);
            }
            #pragma unroll
            for (int mt = 0; mt < 2; mt++)
                #pragma unroll
                for (int nt = 0; nt < 7; nt++)
                    MMA_TF32(acc[mt][nt], af[mt][0], af[mt][1], af[mt][2], af[mt][3],
                             bf[nt][0], bf[nt][1]);
        }
        if (it + 2 < 7) issue((it + 2) * 32, (it + 2) % NSTAGE);
    }
}

// ---------------- kernel 1: QKV + permute + q*SCALE (outputs tf32-rounded) ----------------
__global__ __launch_bounds__(256, 2) void qkv_kernel()
{
    extern __shared__ float smem[];
    float acc[2][7][4] = {};
    const int ctan = blockIdx.x, ctam = blockIdx.y;

    const float* B; int ldb, ncol0;
    if (ctan < 2) { B = g_Wq;  ldb = 224; ncol0 = ctan * 112; }
    else          { B = g_Wkv; ldb = 448; ncol0 = ctan * 112 - 224; }

    gemm_mainloop(g_X + (size_t)ctam * 128 * CDIM, B, ldb, ncol0, smem, acc);

    float* Dst = (ctan < 2) ? g_Q : (ctan < 4 ? g_K : g_V);
    const float scale = (ctan < 2) ? SCALE_Q : 1.0f;
    const int tid = threadIdx.x, wid = tid >> 5, lane = tid & 31;
    const int g = lane >> 2, tig = lane & 3, wm = wid >> 1, wn = wid & 1;
    const int joff = (ctan & 1) * 112 + wn * 56 + tig * 2;

    #pragma unroll
    for (int mt = 0; mt < 2; mt++)
        #pragma unroll
        for (int rh = 0; rh < 2; rh++) {
            int r = wm * 32 + mt * 16 + rh * 8 + g;
            int t = ctam * 128 + r;
            int b = t >> 10, hr = (t >> 5) & 31, wc = t & 31;
            int n = ((hr >> 3) << 2) + (wc >> 3);
            int i = ((hr & 7) << 3) + (wc & 7);
            float* base = Dst + ((size_t)((b * 16 + n) * 64 + i)) * CDIM + joff;
            #pragma unroll
            for (int nt = 0; nt < 7; nt++)
                *reinterpret_cast<float2*>(base + nt * 8) = make_float2(
                    tf32f(acc[mt][nt][rh * 2 + 0] * scale),
                    tf32f(acc[mt][nt][rh * 2 + 1] * scale));
        }
}

// ---------------- kernel 2: local window attention, tensor cores ----------------
// 128 threads = 4 warps; warp w owns rows 16w..16w+15 of the 64x64 attention
__global__ __launch_bounds__(128) void local_attn(const float* __restrict__ pe1)
{
    __shared__ float sQ[64 * 36];    // [m][k], k-pad 28..31 zero
    __shared__ float sKT[32 * 68];   // [k][n], k-pad rows 28..31 zero
    __shared__ float sV[64 * 36];    // [j][c], c-pad 28..31 zero
    __shared__ float sP[64 * 68];    // [m][j] tf32

    const int tid = threadIdx.x;
    const int wid = tid >> 5, lane = tid & 31;
    const int g = lane >> 2, tig = lane & 3;
    const int m0 = wid * 16;
    const size_t rowbase = (size_t)blockIdx.x * 64 * CDIM;

    // zero pads once (loads never touch them)
    for (int i = tid; i < 64 * 4; i += 128) {
        sQ[(i >> 2) * 36 + 28 + (i & 3)] = 0.f;
        sV[(i >> 2) * 36 + 28 + (i & 3)] = 0.f;
    }
    for (int i = tid; i < 4 * 68; i += 128) sKT[28 * 68 + i] = 0.f;
    __syncthreads();

    for (int h = 0; h < 4; h++) {
        const int ch0 = h * 28;
        // load Q,K,V tiles (448 float4 slots)
        #pragma unroll
        for (int p = 0; p < 4; p++) {
            int idx = tid + p * 128;
            if (idx < 448) {
                int rr = idx / 7, c4 = (idx % 7) << 2;
                size_t ga = rowbase + (size_t)rr * CDIM + ch0 + c4;
                *reinterpret_cast<float4*>(sQ + rr * 36 + c4) =
                    *reinterpret_cast<const float4*>(g_Q + ga);
                float4 k4 = *reinterpret_cast<const float4*>(g_K + ga);
                sKT[(c4 + 0) * 68 + rr] = k4.x; sKT[(c4 + 1) * 68 + rr] = k4.y;
                sKT[(c4 + 2) * 68 + rr] = k4.z; sKT[(c4 + 3) * 68 + rr] = k4.w;
                *reinterpret_cast<float4*>(sV + rr * 36 + c4) =
                    *reinterpret_cast<const float4*>(g_V + ga);
            }
        }
        __syncthreads();

        // ---- S = Q K^T : 1 m-tile x 8 n-tiles x 4 k-steps per warp ----
        float accS[8][4];
        #pragma unroll
        for (int nt = 0; nt < 8; nt++)
            #pragma unroll
            for (int e = 0; e < 4; e++) accS[nt][e] = 0.f;
        #pragma unroll
        for (int ks = 0; ks < 4; ks++) {
            const int kb = ks * 8;
            unsigned a0 = __float_as_uint(sQ[(m0 + g) * 36 + kb + tig]);
            unsigned a1 = __float_as_uint(sQ[(m0 + 8 + g) * 36 + kb + tig]);
            unsigned a2 = __float_as_uint(sQ[(m0 + g) * 36 + kb + tig + 4]);
            unsigned a3 = __float_as_uint(sQ[(m0 + 8 + g) * 36 + kb + tig + 4]);
            #pragma unroll
            for (int nt = 0; nt < 8; nt++) {
                unsigned b0 = __float_as_uint(sKT[(kb + tig) * 68 + nt * 8 + g]);
                unsigned b1 = __float_as_uint(sKT[(kb + tig + 4) * 68 + nt * 8 + g]);
                MMA_TF32(accS[nt], a0, a1, a2, a3, b0, b1);
            }
        }

        // ---- + pos_emb1, softmax on fragments (rows r0=m0+g, r1=m0+8+g) ----
        const float* pe = pe1 + (size_t)h * 4096;
        #pragma unroll
        for (int nt = 0; nt < 8; nt++) {
            float2 p0 = *reinterpret_cast<const float2*>(pe + (m0 + g) * 64 + nt * 8 + 2 * tig);
            float2 p1 = *reinterpret_cast<const float2*>(pe + (m0 + 8 + g) * 64 + nt * 8 + 2 * tig);
            accS[nt][0] += p0.x; accS[nt][1] += p0.y;
            accS[nt][2] += p1.x; accS[nt][3] += p1.y;
        }
        float m0v = -1e30f, m1v = -1e30f;
        #pragma unroll
        for (int nt = 0; nt < 8; nt++) {
            m0v = fmaxf(m0v, fmaxf(accS[nt][0], accS[nt][1]));
            m1v = fmaxf(m1v, fmaxf(accS[nt][2], accS[nt][3]));
        }
        m0v = fmaxf(m0v, __shfl_xor_sync(0xffffffffu, m0v, 1));
        m0v = fmaxf(m0v, __shfl_xor_sync(0xffffffffu, m0v, 2));
        m1v = fmaxf(m1v, __shfl_xor_sync(0xffffffffu, m1v, 1));
        m1v = fmaxf(m1v, __shfl_xor_sync(0xffffffffu, m1v, 2));
        float s0 = 0.f, s1 = 0.f;
        #pragma unroll
        for (int nt = 0; nt < 8; nt++) {
            accS[nt][0] = __expf(accS[nt][0] - m0v); s0 += accS[nt][0];
            accS[nt][1] = __expf(accS[nt][1] - m0v); s0 += accS[nt][1];
            accS[nt][2] = __expf(accS[nt][2] - m1v); s1 += accS[nt][2];
            accS[nt][3] = __expf(accS[nt][3] - m1v); s1 += accS[nt][3];
        }
        s0 += __shfl_xor_sync(0xffffffffu, s0, 1);
        s0 += __shfl_xor_sync(0xffffffffu, s0, 2);
        s1 += __shfl_xor_sync(0xffffffffu, s1, 1);
        s1 += __shfl_xor_sync(0xffffffffu, s1, 2);
        const float i0 = 1.f / s0, i1 = 1.f / s1;
        #pragma unroll
        for (int nt = 0; nt < 8; nt++) {
            *reinterpret_cast<float2*>(sP + (m0 + g) * 68 + nt * 8 + 2 * tig) =
                make_float2(tf32f(accS[nt][0] * i0), tf32f(accS[nt][1] * i0));
            *reinterpret_cast<float2*>(sP + (m0 + 8 + g) * 68 + nt * 8 + 2 * tig) =
                make_float2(tf32f(accS[nt][2] * i1), tf32f(accS[nt][3] * i1));
        }
        __syncwarp();

        // ---- O = P V : 1 m-tile x 4 n-tiles x 8 k-steps per warp ----
        float accO[4][4];
        #pragma unroll
        for (int nt = 0; nt < 4; nt++)
            #pragma unroll
            for (int e = 0; e < 4; e++) accO[nt][e] = 0.f;
        #pragma unroll
        for (int ks = 0; ks < 8; ks++) {
            const int kb = ks * 8;
            unsigned a0 = __float_as_uint(sP[(m0 + g) * 68 + kb + tig]);
            unsigned a1 = __float_as_uint(sP[(m0 + 8 + g) * 68 + kb + tig]);
            unsigned a2 = __float_as_uint(sP[(m0 + g) * 68 + kb + tig + 4]);
            unsigned a3 = __float_as_uint(sP[(m0 + 8 + g) * 68 + kb + tig + 4]);
            #pragma unroll
            for (int nt = 0; nt < 4; nt++) {
                unsigned b0 = __float_as_uint(sV[(kb + tig) * 36 + nt * 8 + g]);
                unsigned b1 = __float_as_uint(sV[(kb + tig + 4) * 36 + nt * 8 + g]);
                MMA_TF32(accO[nt], a0, a1, a2, a3, b0, b1);
            }
        }
        // store O (tf32-rounded for proj GEMM); cols >= 28 are pad
        #pragma unroll
        for (int nt = 0; nt < 4; nt++) {
            int col = nt * 8 + 2 * tig;
            if (col < 28) {
                *reinterpret_cast<float2*>(g_Attn + rowbase + (size_t)(m0 + g) * CDIM + ch0 + col) =
                    make_float2(tf32f(accO[nt][0]), tf32f(accO[nt][1]));
                *reinterpret_cast<float2*>(g_Attn + rowbase + (size_t)(m0 + 8 + g) * CDIM + ch0 + col) =
                    make_float2(tf32f(accO[nt][2]), tf32f(accO[nt][3]));
            }
        }
        __syncthreads();
    }
}

// ---------------- kernel 3: global attention (channels 112..223) ----------------
__global__ __launch_bounds__(128) void global_attn(const float* __restrict__ pe2)
{
    __shared__ float qs[16 * 116];
    __shared__ float kTs[112 * 20];
    __shared__ float vs[16 * 116];
    __shared__ float ps[4 * 16 * 17];

    const int tid = threadIdx.x;
    const int b = blockIdx.x >> 6, ipos = blockIdx.x & 63;
    const size_t base0 = ((size_t)(b * 16) * 64 + ipos) * CDIM + 112;

    #pragma unroll
    for (int p = 0; p < 4; p++) {
        int idx = tid + p * 128;
        if (idx < 448) {
            int n = idx / 28, c4 = (idx % 28) << 2;
            size_t ga = base0 + (size_t)n * (64 * CDIM) + c4;
            *reinterpret_cast<float4*>(qs + n * 116 + c4) = *reinterpret_cast<const float4*>(g_Q + ga);
            *reinterpret_cast<float4*>(vs + n * 116 + c4) = *reinterpret_cast<const float4*>(g_V + ga);
            float4 k4 = *reinterpret_cast<const float4*>(g_K + ga);
            kTs[(c4 + 0) * 20 + n] = k4.x; kTs[(c4 + 1) * 20 + n] = k4.y;
            kTs[(c4 + 2) * 20 + n] = k4.z; kTs[(c4 + 3) * 20 + n] = k4.w;
        }
    }
    __syncthreads();

    const int h = tid >> 5, lane = tid & 31;
    const int r = lane >> 1, cb = (lane & 1) << 3;

    float qreg[28];
    #pragma unroll
    for (int u = 0; u < 7; u++) {
        float4 f = *reinterpret_cast<float4*>(qs + r * 116 + h * 28 + 4 * u);
        qreg[4 * u] = f.x; qreg[4 * u + 1] = f.y; qreg[4 * u + 2] = f.z; qreg[4 * u + 3] = f.w;
    }
    float s[8];
    #pragma unroll
    for (int j = 0; j < 8; j++) s[j] = 0.f;
    #pragma unroll
    for (int d = 0; d < 28; d++)
        #pragma unroll
        for (int j = 0; j < 8; j++) s[j] += qreg[d] * kTs[(h * 28 + d) * 20 + cb + j];

    const float* pr = pe2 + (size_t)h * 256 + r * 16 + cb;
    #pragma unroll
    for (int j = 0; j < 8; j++) s[j] += pr[j];
    float m = s[0];
    #pragma unroll
    for (int j = 1; j < 8; j++) m = fmaxf(m, s[j]);
    m = fmaxf(m, __shfl_xor_sync(0xffffffffu, m, 1));
    float sum = 0.f;
    #pragma unroll
    for (int j = 0; j < 8; j++) { s[j] = __expf(s[j] - m); sum += s[j]; }
    sum += __shfl_xor_sync(0xffffffffu, sum, 1);
    const float inv = 1.f / sum;
    #pragma unroll
    for (int j = 0; j < 8; j++) ps[h * 272 + r * 17 + cb + j] = s[j] * inv;
    __syncwarp();

    const int chb = (lane & 1) * 14;
    float accO[14];
    #pragma unroll
    for (int c = 0; c < 14; c++) accO[c] = 0.f;
    #pragma unroll
    for (int j = 0; j < 16; j++) {
        float p = ps[h * 272 + r * 17 + j];
        #pragma unroll
        for (int c = 0; c < 14; c++) accO[c] += p * vs[j * 116 + h * 28 + chb + c];
    }
    float* od = g_Attn + ((size_t)((b * 16 + r) * 64 + ipos)) * CDIM + 112 + h * 28 + chb;
    #pragma unroll
    for (int c = 0; c < 14; c++) od[c] = tf32f(accO[c]);
}

// ---------------- kernel 4: out-proj + bias + window-reverse ----------------
__global__ __launch_bounds__(256, 2) void proj_kernel(
    const float* __restrict__ bout, float* __restrict__ out)
{
    extern __shared__ float smem[];
    float acc[2][7][4] = {};
    const int ctan = blockIdx.x, ctam = blockIdx.y;

    gemm_mainloop(g_Attn + (size_t)ctam * 128 * CDIM, g_Wout, 224, ctan * 112, smem, acc);

    const int tid = threadIdx.x, wid = tid >> 5, lane = tid & 31;
    const int g = lane >> 2, tig = lane & 3, wm = wid >> 1, wn = wid & 1;
    const int joff = ctan * 112 + wn * 56 + tig * 2;

    #pragma unroll
    for (int mt = 0; mt < 2; mt++)
        #pragma unroll
        for (int rh = 0; rh < 2; rh++) {
            int r = wm * 32 + mt * 16 + rh * 8 + g;
            int t = ctam * 128 + r;
            int b = t >> 10, n = (t >> 6) & 15, i = t & 63;
            int hr = (n >> 2) * 8 + (i >> 3), wc = (n & 3) * 8 + (i & 7);
            float* base = out + ((size_t)((b * 32 + hr) * 32 + wc)) * CDIM + joff;
            #pragma unroll
            for (int nt = 0; nt < 7; nt++) {
                float2 bo = *reinterpret_cast<const float2*>(bout + joff + nt * 8);
                *reinterpret_cast<float2*>(base + nt * 8) =
                    make_float2(acc[mt][nt][rh * 2 + 0] + bo.x, acc[mt][nt][rh * 2 + 1] + bo.y);
            }
        }
}

extern "C" void kernel_launch(void* const* d_in, const int* in_sizes, int n_in,
                              void* d_out, int out_size) {
    const float* x    = (const float*)d_in[0];
    const float* Wq   = (const float*)d_in[1];
    const float* Wkv  = (const float*)d_in[2];
    const float* Wout = (const float*)d_in[3];
    const float* bout = (const float*)d_in[4];
    const float* pe1  = (const float*)d_in[5];
    const float* pe2  = (const float*)d_in[6];
    float* out = (float*)d_out;

    cudaFuncSetAttribute(qkv_kernel,  cudaFuncAttributeMaxDynamicSharedMemorySize, GEMM_SMEM_BYTES);
    cudaFuncSetAttribute(proj_kernel, cudaFuncAttributeMaxDynamicSharedMemorySize, GEMM_SMEM_BYTES);

    float* gX;    cudaGetSymbolAddress((void**)&gX,    g_X);
    float* gWq;   cudaGetSymbolAddress((void**)&gWq,   g_Wq);
    float* gWkv;  cudaGetSymbolAddress((void**)&gWkv,  g_Wkv);
    float* gWout; cudaGetSymbolAddress((void**)&gWout, g_Wout);

    round_tf32<<<28672, 256>>>(x, gX, 29360128 / 4);
    round_tf32<<<49, 256>>>(Wq, gWq, 50176 / 4);
    round_tf32<<<98, 256>>>(Wkv, gWkv, 100352 / 4);
    round_tf32<<<49, 256>>>(Wout, gWout, 50176 / 4);

    qkv_kernel<<<dim3(6, 1024), 256, GEMM_SMEM_BYTES>>>();
    local_attn<<<2048, 128>>>(pe1);
    global_attn<<<8192, 128>>>(pe2);
    proj_kernel<<<dim3(2, 1024), 256, GEMM_SMEM_BYTES>>>(bout, out);
}